// round 14
// baseline (speedup 1.0000x reference)
#include <cuda_runtime.h>
#include <cuda_bf16.h>
#include <cstdint>

#define HO 190
#define WO 190
#define XROW 8448                 // 66 cols x 128B per (slot,pass) row
#define XS_BYTES (4 * 2 * XROW)   // 67584
#define BF_OFF XS_BYTES
#define BF_BYTES 147456           // 36 ksteps x 16 ntiles x 32 lanes x 8B
#define DS_OFF (BF_OFF + BF_BYTES)
#define SMEM_TOTAL (DS_OFF + 64 * 68 * 4)   // 232448 = 227KB exactly

typedef unsigned long long ull;

__device__ float g_Wd[64 * 9 * 64];                     // [o][tap][i]
__device__ unsigned g_B[36 * 16 * 32 * 2];              // b-frags, reg order
__device__ __align__(16) __nv_bfloat16 g_xh[4ull * 192 * 192 * 64]; // [b][h][w][i]
__device__ __align__(16) __nv_bfloat16 g_xl[4ull * 192 * 192 * 64];

__device__ __forceinline__ void cpa16(uint32_t d, const void* s) {
    asm volatile("cp.async.ca.shared.global [%0], [%1], 16;" :: "r"(d), "l"(s));
}
#define CPCOMMIT() asm volatile("cp.async.commit_group;")
#define CPWAIT0()  asm volatile("cp.async.wait_group 0;")

// ------------------------- prep kernels -------------------------
__global__ void k_zero() {
    int i = blockIdx.x * 1024 + threadIdx.x;
    if (i < 64 * 9 * 64) g_Wd[i] = 0.0f;
}
__global__ void k_scatter(const float* __restrict__ w, const int* __restrict__ cin,
                          const int* __restrict__ cout, int K) {
    int k = blockIdx.x * 256 + threadIdx.x;
    if (k < K) {
        int o = cout[k], i = cin[k];
#pragma unroll
        for (int t = 0; t < 9; t++)
            atomicAdd(&g_Wd[(o * 9 + t) * 64 + i], w[k * 9 + t]);
    }
}
// B-frags for mma.m16n8k16 (B col-major frag: lane holds n = lane/4,
// k = kstep*16 + (lane%4)*2 (+1), reg1 at k+8). n<64 -> bf16-hi(W), n>=64 -> lo.
__global__ void k_buildB() {
    int idx = blockIdx.x * 256 + threadIdx.x;   // 36*16*32 = 18432
    if (idx >= 18432) return;
    int lane = idx & 31, nt = (idx >> 5) & 15, ks = idx >> 9;
    int n = nt * 8 + (lane >> 2);
    int o = n & 63;
    bool lo = n >= 64;
    int kk = ks * 16 + (lane & 3) * 2;
#pragma unroll
    for (int rr = 0; rr < 2; rr++) {
        unsigned pk = 0;
#pragma unroll
        for (int e = 0; e < 2; e++) {
            int k = kk + rr * 8 + e;
            int tap = k >> 6, i = k & 63;
            float v = g_Wd[(o * 9 + tap) * 64 + i];
            __nv_bfloat16 h = __float2bfloat16(v);
            __nv_bfloat16 val = lo ? __float2bfloat16(v - __bfloat162float(h)) : h;
            pk |= (unsigned)__bfloat16_as_ushort(val) << (16 * e);
        }
        g_B[idx * 2 + rr] = pk;
    }
}
// x -> channel-last bf16 hi/lo: g_xh/g_xl[b][h][w][i], 128B per (h,w).
__global__ void k_transpose(const float* __restrict__ x) {
    __shared__ float sm[64 * 192];
    int h = blockIdx.x, b = blockIdx.y, t = threadIdx.x;
    for (int idx = t; idx < 64 * 192; idx += 256) {
        int i = idx / 192, w = idx % 192;
        sm[idx] = x[(((size_t)b * 64 + i) * 192 + h) * 192 + w];
    }
    __syncthreads();
    if (t < 192) {
        unsigned hv[32], lv[32];
#pragma unroll
        for (int q = 0; q < 32; q++) {
            float f0 = sm[(2 * q) * 192 + t], f1 = sm[(2 * q + 1) * 192 + t];
            __nv_bfloat16 h0 = __float2bfloat16(f0), h1 = __float2bfloat16(f1);
            __nv_bfloat16 l0 = __float2bfloat16(f0 - __bfloat162float(h0));
            __nv_bfloat16 l1 = __float2bfloat16(f1 - __bfloat162float(h1));
            hv[q] = (unsigned)__bfloat16_as_ushort(h0) | ((unsigned)__bfloat16_as_ushort(h1) << 16);
            lv[q] = (unsigned)__bfloat16_as_ushort(l0) | ((unsigned)__bfloat16_as_ushort(l1) << 16);
        }
        size_t base = (((size_t)b * 192 + h) * 192 + t) * 32;   // u32 units
        uint4* dh = (uint4*)g_xh + base / 4;
        uint4* dl = (uint4*)g_xl + base / 4;
#pragma unroll
        for (int q = 0; q < 8; q++) {
            dh[q] = make_uint4(hv[4*q], hv[4*q+1], hv[4*q+2], hv[4*q+3]);
            dl[q] = make_uint4(lv[4*q], lv[4*q+1], lv[4*q+2], lv[4*q+3]);
        }
    }
}

// ------------------------- conv kernel -------------------------
// grid (3, 19, 4): x = w-strip {0,64,126}, y = 10-row h chunk, z = batch.
// 256 thr / 8 warps; warp tile m32 x n64 of GEMM M=128 (hi|lo px) N=128 (Wh|Wl).
__global__ __launch_bounds__(256, 1)
void conv_mma(const float* __restrict__ bias, float* __restrict__ out) {
    extern __shared__ __align__(16) char smem[];
    uint32_t sb = (uint32_t)__cvta_generic_to_shared(smem);
    int tid = threadIdx.x, lane = tid & 31, warp = tid >> 5;
    int wm = warp >> 1, wn = warp & 1;       // wm: m-strip 0..3, wn: n-half
    int pass = wm >> 1;                       // 0 = hi px, 1 = lo px
    int pbase = (wm & 1) * 32;                // pixel base within 64

    int b = blockIdx.z, h0 = blockIdx.y * 10;
    int w0 = (blockIdx.x == 0) ? 0 : (blockIdx.x == 1 ? 64 : 126);

    const __nv_bfloat16* xh = g_xh + (size_t)b * 192 * 192 * 64;
    const __nv_bfloat16* xl = g_xl + (size_t)b * 192 * 192 * 64;

    // Stage full B-frag table (144 KB) once.
    for (int cc = tid; cc < BF_BYTES / 16; cc += 256)
        cpa16(sb + BF_OFF + cc * 16, (const char*)g_B + cc * 16);

    // Stage one (h-row, both passes): 66 cols x 8 chunks, XOR-swizzled.
#define STAGE(hh) do {                                                         \
        int _s = (hh) & 3;                                                     \
        const __nv_bfloat16* s0 = xh + (((size_t)(hh)) * 192 + w0) * 64;       \
        const __nv_bfloat16* s1 = xl + (((size_t)(hh)) * 192 + w0) * 64;       \
        for (int cc = tid; cc < 528; cc += 256) {                              \
            int ws_ = cc >> 3, j = cc & 7;                                     \
            uint32_t dof = (uint32_t)(ws_ * 128 + ((j ^ (ws_ & 7)) * 16));     \
            cpa16(sb + (uint32_t)((_s * 2 + 0) * XROW) + dof,                  \
                  (const char*)s0 + ws_ * 128 + j * 16);                       \
            cpa16(sb + (uint32_t)((_s * 2 + 1) * XROW) + dof,                  \
                  (const char*)s1 + ws_ * 128 + j * 16);                       \
        } } while (0)

    STAGE(h0); STAGE(h0 + 1); STAGE(h0 + 2);
    CPCOMMIT();

    float* Ds = (float*)(smem + DS_OFF);     // [64 px][68] fp32

    for (int r = 0; r < 10; r++) {
        int h = h0 + r;
        CPWAIT0();
        __syncthreads();
        if (r < 9) STAGE(h + 3);             // overwrites slot (h-1)&3 (free)
        CPCOMMIT();

        float acc[2][8][4];
#pragma unroll
        for (int mt = 0; mt < 2; mt++)
#pragma unroll
            for (int nt = 0; nt < 8; nt++)
#pragma unroll
                for (int e = 0; e < 4; e++) acc[mt][nt][e] = 0.0f;

#pragma unroll
        for (int tap = 0; tap < 9; tap++) {
            const int dh = tap / 3, dw = tap % 3;
            int slot = (h + dh) & 3;
            uint32_t arow = sb + (uint32_t)((slot * 2 + pass) * XROW);
#pragma unroll
            for (int sub = 0; sub < 4; sub++) {
                int ks = tap * 4 + sub;
                // B frags for this warp's n-half (same for both m-tiles).
                unsigned bf[8][2];
#pragma unroll
                for (int nt = 0; nt < 8; nt++) {
                    uint2 bv = *(const uint2*)(smem + BF_OFF +
                        (((size_t)(ks * 16 + wn * 8 + nt) * 32 + lane) << 3));
                    bf[nt][0] = bv.x; bf[nt][1] = bv.y;
                }
                // A frags via ldmatrix.x4 (m16k16 each).
                unsigned af[2][4];
#pragma unroll
                for (int mt = 0; mt < 2; mt++) {
                    int px = pbase + mt * 16 + (lane & 15);
                    int wl = px + dw;
                    int kc = lane >> 4;
                    uint32_t ad = arow + (uint32_t)(wl * 128 +
                                  (((sub * 2 + kc) ^ (wl & 7)) * 16));
                    asm volatile(
                        "ldmatrix.sync.aligned.m8n8.x4.shared.b16 {%0,%1,%2,%3}, [%4];"
                        : "=r"(af[mt][0]), "=r"(af[mt][1]),
                          "=r"(af[mt][2]), "=r"(af[mt][3]) : "r"(ad));
                }
#pragma unroll
                for (int mt = 0; mt < 2; mt++)
#pragma unroll
                    for (int nt = 0; nt < 8; nt++)
                        asm volatile(
                            "mma.sync.aligned.m16n8k16.row.col.f32.bf16.bf16.f32 "
                            "{%0,%1,%2,%3}, {%4,%5,%6,%7}, {%8,%9}, {%0,%1,%2,%3};"
                            : "+f"(acc[mt][nt][0]), "+f"(acc[mt][nt][1]),
                              "+f"(acc[mt][nt][2]), "+f"(acc[mt][nt][3])
                            : "r"(af[mt][0]), "r"(af[mt][1]),
                              "r"(af[mt][2]), "r"(af[mt][3]),
                              "r"(bf[nt][0]), "r"(bf[nt][1]));
            }
        }

        // Epilogue: y = D[hi,Wh] + D[hi,Wl] + D[lo,Wh] via Dstage.
        // Common frag coords: px = pbase + mt*16 + lane/4 (+8), o = nt*8 + (lane%4)*2.
#define FRAG_LOOP(...)                                                         \
        _Pragma("unroll")                                                      \
        for (int mt = 0; mt < 2; mt++) {                                       \
            int r0 = pbase + mt * 16 + (lane >> 2);                            \
            _Pragma("unroll")                                                  \
            for (int nt = 0; nt < 8; nt++) {                                   \
                int c = nt * 8 + (lane & 3) * 2;                               \
                float2* p0 = (float2*)&Ds[r0 * 68 + c];                        \
                float2* p1 = (float2*)&Ds[(r0 + 8) * 68 + c];                  \
                __VA_ARGS__;                                                   \
            }                                                                  \
        }
        if (wm < 2 && wn == 0)   // hi px * Wh : store
            FRAG_LOOP(*p0 = make_float2(acc[mt][nt][0], acc[mt][nt][1]);
                      *p1 = make_float2(acc[mt][nt][2], acc[mt][nt][3]));
        __syncthreads();
        if (wm < 2 && wn == 1)   // hi px * Wl : add
            FRAG_LOOP(float2 v0 = *p0;
                      float2 v1 = *p1;
                      v0.x += acc[mt][nt][0]; v0.y += acc[mt][nt][1];
                      v1.x += acc[mt][nt][2]; v1.y += acc[mt][nt][3];
                      *p0 = v0; *p1 = v1);
        __syncthreads();
        if (wm >= 2 && wn == 0)  // lo px * Wh : add
            FRAG_LOOP(float2 v0 = *p0;
                      float2 v1 = *p1;
                      v0.x += acc[mt][nt][0]; v0.y += acc[mt][nt][1];
                      v1.x += acc[mt][nt][2]; v1.y += acc[mt][nt][3];
                      *p0 = v0; *p1 = v1);
        __syncthreads();

        // Store: thread t -> o = t/4, px chunk (t%4)*16, 8 float2 per thread.
        {
            int o = tid >> 2, px0 = (tid & 3) * 16;
            float bv = bias[o];
            float* op = out + (((size_t)(b * 64 + o)) * HO + h) * WO + w0 + px0;
#pragma unroll
            for (int q = 0; q < 16; q += 2) {
                float2 v;
                v.x = Ds[(px0 + q) * 68 + o] + bv;
                v.y = Ds[(px0 + q + 1) * 68 + o] + bv;
                *(float2*)(op + q) = v;
            }
        }
        __syncthreads();   // Dstage free before next row
    }
}

// ---------------------------------------------------------------------------
extern "C" void kernel_launch(void* const* d_in, const int* in_sizes, int n_in,
                              void* d_out, int out_size) {
    const float* x    = (const float*)d_in[0];
    const float* w    = (const float*)d_in[1];
    const float* bias = (const float*)d_in[2];
    const int*   cin  = (const int*)d_in[3];
    const int*   cout = (const int*)d_in[4];
    int K = in_sizes[3];
    int B = in_sizes[0] / (64 * 192 * 192);

    cudaFuncSetAttribute(conv_mma, cudaFuncAttributeMaxDynamicSharedMemorySize,
                         SMEM_TOTAL);

    k_zero<<<(64 * 9 * 64 + 1023) / 1024, 1024>>>();
    k_scatter<<<(K + 255) / 256, 256>>>(w, cin, cout, K);
    k_buildB<<<(18432 + 255) / 256, 256>>>();
    dim3 tg(192, B);
    k_transpose<<<tg, 256>>>(x);
    dim3 grid(3, 19, B);
    conv_mma<<<grid, 256, SMEM_TOTAL>>>(bias, (float*)d_out);
}